// round 16
// baseline (speedup 1.0000x reference)
#include <cuda_runtime.h>
#include <cuda_fp16.h>
#include <mma.h>
#include <math.h>

using namespace nvcuda;

#define NN 100000
#define NNP 100096
#define E_RAW 800000
#define E_TOT 900000
#define F_IN 300
#define KXP 304
#define C1 256
#define C2 128
#define F3 64
#define OUTC 4
#define SCAN_B 1024
#define NBLK ((NN + SCAN_B - 1) / SCAN_B)   // 98
#define MSPLIT 391                          // row-block split: 391*128 = 50048
#define NSPLIT (MSPLIT * 128)               // node split for chunked overlap

// ---------------- scratch ----------------
__device__ __half g_hsrch[(long)NNP * C1];
__device__ __half g_out1h[(long)NNP * C1];
__device__ __half g_hsrc2h[(long)NNP * C2];
__device__ __half g_out2h[(long)NNP * C2];   // pad rows stay 0 (zero-init, never written)
__device__ float  g_h3[(long)NNP * F3];
// fp16 weights
__device__ __half g_wlinh[KXP * C1];
__device__ __half g_w1h[C1 * C1];
__device__ __half g_w2h[C1 * C2];
__device__ __half g_wfh[C2 * F3];
// attention
__device__ float g_as[NN], g_ad[NN];
__device__ float g_as2[NN], g_ad2[NN];
__device__ float g_v1s[C1], g_v1d[C1], g_v2s[C1], g_v2d[C1];
__device__ float g_bnsum[F3], g_bnsq[F3];
// CSR
__device__ int g_deg[NN];
__device__ int g_cur[NN];
__device__ int g_rowptr[NN + 1];
__device__ int g_bsum[NBLK];
__device__ int g_csrc[E_TOT];

// ---------------- cp.async helpers ----------------
__device__ __forceinline__ void cp_async16(void* smem_dst, const void* gsrc, int src_bytes) {
    unsigned saddr = (unsigned)__cvta_generic_to_shared(smem_dst);
    asm volatile("cp.async.cg.shared.global [%0], [%1], 16, %2;"
                 :: "r"(saddr), "l"(gsrc), "r"(src_bytes));
}
__device__ __forceinline__ void cp_commit() {
    asm volatile("cp.async.commit_group;");
}

// ---------------- prep: weight conversions + zeroing + attention matvecs ----------------
__global__ void prep_k(const float* __restrict__ linw, const float* __restrict__ w1s,
                       const float* __restrict__ w2s, const float* __restrict__ fc1w,
                       const float* __restrict__ a1s, const float* __restrict__ w1d,
                       const float* __restrict__ a1d, const float* __restrict__ a2s,
                       const float* __restrict__ w2d, const float* __restrict__ a2d) {
    int i = blockIdx.x * blockDim.x + threadIdx.x;
    if (i < KXP * C1) {
        int r = i / C1;
        g_wlinh[i] = __float2half(r < F_IN ? linw[i] : 0.f);
    }
    if (i < C1 * C1) g_w1h[i] = __float2half(w1s[i]);
    if (i < C1 * C2) g_w2h[i] = __float2half(w2s[i]);
    if (i < C2 * F3) g_wfh[i] = __float2half(fc1w[i]);
    if (i < NN) { g_deg[i] = 0; g_cur[i] = 0; }
    if (i < F3) { g_bnsum[i] = 0.f; g_bnsq[i] = 0.f; }

    if (blockIdx.x < 128) {
        int gw = blockIdx.x * 8 + (threadIdx.x >> 5);
        int lane = threadIdx.x & 31;
        const float *W, *a; float* v; int cols, row;
        if (gw < C1)            { W = w1s; a = a1s; v = g_v1s; cols = C1; row = gw; }
        else if (gw < 2 * C1)   { W = w1d; a = a1d; v = g_v1d; cols = C1; row = gw - C1; }
        else if (gw < 3 * C1)   { W = w2s; a = a2s; v = g_v2s; cols = C2; row = gw - 2 * C1; }
        else                    { W = w2d; a = a2d; v = g_v2d; cols = C2; row = gw - 3 * C1; }
        float s = 0.f;
        for (int c = lane; c < cols; c += 32) s += W[(long)row * cols + c] * a[c];
#pragma unroll
        for (int o = 16; o > 0; o >>= 1) s += __shfl_down_sync(0xffffffffu, s, o);
        if (lane == 0) v[row] = s;
    }
}

#define NSTAGE 3
#define FAP 40
#define FBP 264
#define H0P 264

// ---------------- fused: h0=relu(x@Wlin+b) -> as/ad -> hsrc=h0@W1s ----------------
__global__ void __launch_bounds__(256, 2)
fused_l01(const float* __restrict__ x, const float* __restrict__ linb) {
    __shared__ __align__(16) __half As[2][64][FAP];
    __shared__ __align__(16) __half Bs[NSTAGE][32][FBP];
    __shared__ __align__(16) __half H0[64][H0P];
    __shared__ float stage[8][16][20];

    const int tid = threadIdx.x;
    const int wid = tid >> 5;
    const int lane = tid & 31;
    const int wr = wid >> 2;
    const int wc = wid & 3;
    const int bm = blockIdx.x * 64;
    const int am = tid >> 2;
    const int akq = tid & 3;

    const int arow = bm + am;
    const bool rowok = arow < NN;
    const float* xrow = x + (long)arow * F_IN + akq * 8;

    // ---------- phase 1: H0 = relu(x @ Wlin + b) ----------
    {
        wmma::fragment<wmma::accumulator, 16, 16, 16, float> acc[2][4];
#pragma unroll
        for (int i = 0; i < 2; i++)
#pragma unroll
            for (int j = 0; j < 4; j++) wmma::fill_fragment(acc[i][j], 0.f);

        float areg[8];
        auto ld_a = [&](int kt) {
            if (rowok && kt < 9) {
                const float4* p = reinterpret_cast<const float4*>(xrow + kt * 32);
                float4 u = p[0], v = p[1];
                areg[0] = u.x; areg[1] = u.y; areg[2] = u.z; areg[3] = u.w;
                areg[4] = v.x; areg[5] = v.y; areg[6] = v.z; areg[7] = v.w;
            } else if (rowok) {
                int cbase = kt * 32 + akq * 8;
#pragma unroll
                for (int t = 0; t < 8; t++)
                    areg[t] = (cbase + t < F_IN) ? xrow[kt * 32 + t] : 0.f;
            } else {
#pragma unroll
                for (int t = 0; t < 8; t++) areg[t] = 0.f;
            }
        };
        auto st_a = [&](int s) {
            __half2 hp[4];
#pragma unroll
            for (int q = 0; q < 4; q++) hp[q] = __floats2half2_rn(areg[2 * q], areg[2 * q + 1]);
            *reinterpret_cast<uint4*>(&As[s][am][akq * 8]) = *reinterpret_cast<uint4*>(hp);
        };
        auto ls1 = [&](int kt, int s) {
            int k0 = kt * 32;
#pragma unroll
            for (int i = 0; i < 4; i++) {
                int idx = tid + i * 256;
                int k = idx >> 5, nq = idx & 31;
                int gk = k0 + k;
                int ok = (gk < KXP) ? 16 : 0;
                cp_async16(&Bs[s][k][nq * 8],
                           g_wlinh + (long)min(gk, KXP - 1) * C1 + nq * 8, ok);
            }
            cp_commit();
        };

        const int KT1 = (KXP + 31) / 32;   // 10
        ld_a(0); st_a(0);
        ls1(0, 0); ls1(1, 1);
        for (int kt = 0; kt < KT1; kt++) {
            int s = kt % NSTAGE;
            if (kt + 1 < KT1) ld_a(kt + 1);
            if (kt + 1 < KT1) asm volatile("cp.async.wait_group 1;");
            else              asm volatile("cp.async.wait_group 0;");
            __syncthreads();
            if (kt + 2 < KT1) ls1(kt + 2, (kt + 2) % NSTAGE);
#pragma unroll
            for (int kk = 0; kk < 32; kk += 16) {
                wmma::fragment<wmma::matrix_a, 16, 16, 16, __half, wmma::row_major> af[2];
#pragma unroll
                for (int i = 0; i < 2; i++)
                    wmma::load_matrix_sync(af[i], &As[kt & 1][wr * 32 + i * 16][kk], FAP);
#pragma unroll
                for (int j = 0; j < 4; j++) {
                    wmma::fragment<wmma::matrix_b, 16, 16, 16, __half, wmma::row_major> bf;
                    wmma::load_matrix_sync(bf, &Bs[s][kk][wc * 64 + j * 16], FBP);
                    wmma::mma_sync(acc[0][j], af[0], bf, acc[0][j]);
                    wmma::mma_sync(acc[1][j], af[1], bf, acc[1][j]);
                }
            }
            if (kt + 1 < KT1) st_a((kt + 1) & 1);
        }
#pragma unroll
        for (int i = 0; i < 2; i++) {
#pragma unroll
            for (int j = 0; j < 4; j++) {
                wmma::store_matrix_sync(&stage[wid][0][0], acc[i][j], 20, wmma::mem_row_major);
                __syncwarp();
                int r = lane >> 1, c0 = (lane & 1) * 8;
                int rl = wr * 32 + i * 16 + r;
                int cl = wc * 64 + j * 16 + c0;
                float v[8];
#pragma unroll
                for (int t = 0; t < 8; t++)
                    v[t] = fmaxf(stage[wid][r][c0 + t] + linb[cl + t], 0.f);
                __half2 hp[4];
#pragma unroll
                for (int q = 0; q < 4; q++) hp[q] = __floats2half2_rn(v[2 * q], v[2 * q + 1]);
                *reinterpret_cast<uint4*>(&H0[rl][cl]) = *reinterpret_cast<uint4*>(hp);
                __syncwarp();
            }
        }
    }
    __syncthreads();

    // ---------- phase 1.5: as/ad = H0 @ v1s / v1d ----------
    {
        const float4* vs4 = reinterpret_cast<const float4*>(g_v1s);
        const float4* vd4 = reinterpret_cast<const float4*>(g_v1d);
#pragma unroll
        for (int r8 = 0; r8 < 8; r8++) {
            int rl = wid * 8 + r8;
            uint4 raw = *reinterpret_cast<const uint4*>(&H0[rl][lane * 8]);
            const __half2* ph = reinterpret_cast<const __half2*>(&raw);
            float s = 0.f, d = 0.f;
#pragma unroll
            for (int q = 0; q < 4; q++) {
                float2 f = __half22float2(ph[q]);
                float4 sv = vs4[lane * 2 + (q >> 1)];
                float4 dv = vd4[lane * 2 + (q >> 1)];
                float svx = (q & 1) ? sv.z : sv.x, svy = (q & 1) ? sv.w : sv.y;
                float dvx = (q & 1) ? dv.z : dv.x, dvy = (q & 1) ? dv.w : dv.y;
                s += f.x * svx + f.y * svy;
                d += f.x * dvx + f.y * dvy;
            }
#pragma unroll
            for (int o = 16; o > 0; o >>= 1) {
                s += __shfl_down_sync(0xffffffffu, s, o);
                d += __shfl_down_sync(0xffffffffu, d, o);
            }
            int grow = bm + rl;
            if (lane == 0 && grow < NN) { g_as[grow] = s; g_ad[grow] = d; }
        }
    }

    // ---------- phase 2: hsrc = H0 @ W1s (A from smem) ----------
    {
        wmma::fragment<wmma::accumulator, 16, 16, 16, float> acc[2][4];
#pragma unroll
        for (int i = 0; i < 2; i++)
#pragma unroll
            for (int j = 0; j < 4; j++) wmma::fill_fragment(acc[i][j], 0.f);

        auto ls2 = [&](int kt, int s) {
            int k0 = kt * 32;
#pragma unroll
            for (int i = 0; i < 4; i++) {
                int idx = tid + i * 256;
                int k = idx >> 5, nq = idx & 31;
                cp_async16(&Bs[s][k][nq * 8],
                           g_w1h + (long)(k0 + k) * C1 + nq * 8, 16);
            }
            cp_commit();
        };

        const int KT2 = C1 / 32;   // 8
        ls2(0, 0); ls2(1, 1);
        for (int kt = 0; kt < KT2; kt++) {
            int s = kt % NSTAGE;
            if (kt + 1 < KT2) asm volatile("cp.async.wait_group 1;");
            else              asm volatile("cp.async.wait_group 0;");
            __syncthreads();
            if (kt + 2 < KT2) ls2(kt + 2, (kt + 2) % NSTAGE);
#pragma unroll
            for (int kk = 0; kk < 32; kk += 16) {
                wmma::fragment<wmma::matrix_a, 16, 16, 16, __half, wmma::row_major> af[2];
#pragma unroll
                for (int i = 0; i < 2; i++)
                    wmma::load_matrix_sync(af[i], &H0[wr * 32 + i * 16][kt * 32 + kk], H0P);
#pragma unroll
                for (int j = 0; j < 4; j++) {
                    wmma::fragment<wmma::matrix_b, 16, 16, 16, __half, wmma::row_major> bf;
                    wmma::load_matrix_sync(bf, &Bs[s][kk][wc * 64 + j * 16], FBP);
                    wmma::mma_sync(acc[0][j], af[0], bf, acc[0][j]);
                    wmma::mma_sync(acc[1][j], af[1], bf, acc[1][j]);
                }
            }
        }
#pragma unroll
        for (int i = 0; i < 2; i++) {
#pragma unroll
            for (int j = 0; j < 4; j++) {
                wmma::store_matrix_sync(&stage[wid][0][0], acc[i][j], 20, wmma::mem_row_major);
                __syncwarp();
                int r = lane >> 1, c0 = (lane & 1) * 8;
                int gr = bm + wr * 32 + i * 16 + r;
                int gc = wc * 64 + j * 16 + c0;
                __half2 hp[4];
#pragma unroll
                for (int q = 0; q < 4; q++)
                    hp[q] = __floats2half2_rn(stage[wid][r][c0 + 2 * q],
                                              stage[wid][r][c0 + 2 * q + 1]);
                *reinterpret_cast<uint4*>(g_hsrch + (long)gr * C1 + gc) =
                    *reinterpret_cast<uint4*>(hp);
                __syncwarp();
            }
        }
    }
}

// ---------------- fp16 GEMM (l2: EPI=0; fc1: EPI=2 fp32-out + fused BN stats) ----------------
// bmoff: row-block offset (for chunked launches).
#define HBK 32
#define HAP 40
template <int BN, int EPI>
__global__ void __launch_bounds__(256, 2)
hgemm_tc(const __half* __restrict__ A, const __half* __restrict__ B,
         void* __restrict__ Cout, int M, int K, int N, int bmoff) {
    constexpr int BP = BN + 8;
    constexpr int WM = (BN == 128) ? 64 : 32;
    constexpr int CG = BN / 32;
    constexpr int MI = WM / 16;
    __shared__ __align__(16) __half As[NSTAGE][128][HAP];
    __shared__ __align__(16) __half Bs[NSTAGE][HBK][BP];
    __shared__ float stage[8][16][20];
    __shared__ float csum[F3], csq[F3];

    const int tid = threadIdx.x;
    const int wid = tid >> 5;
    const int lane = tid & 31;
    const int wr = wid / CG;
    const int wc = wid % CG;
    const int bm = (blockIdx.y + bmoff) * 128;
    const int bn = blockIdx.x * BN;
    const int KT = (K + HBK - 1) / HBK;

    if (EPI == 2 && tid < F3) { csum[tid] = 0.f; csq[tid] = 0.f; }

    wmma::fragment<wmma::accumulator, 16, 16, 16, float> acc[MI][2];
#pragma unroll
    for (int i = 0; i < MI; i++)
#pragma unroll
        for (int j = 0; j < 2; j++) wmma::fill_fragment(acc[i][j], 0.0f);

    auto load_stage = [&](int kt, int s) {
        int k0 = kt * HBK;
#pragma unroll
        for (int i = 0; i < 2; i++) {
            int idx = tid + i * 256;
            int m = idx >> 2, kq = idx & 3;
            int gr = bm + m, gk = k0 + kq * 8;
            int ok = (gr < M && gk < K) ? 16 : 0;
            const __half* src = A + (long)min(gr, M - 1) * K + min(gk, K - 8);
            cp_async16(&As[s][m][kq * 8], src, ok);
        }
#pragma unroll
        for (int i = 0; i < (HBK * BN / 8) / 256; i++) {
            int idx = tid + i * 256;
            int k = idx / (BN / 8), nq = idx % (BN / 8);
            int gk = k0 + k;
            int ok = (gk < K) ? 16 : 0;
            const __half* src = B + (long)min(gk, K - 1) * N + bn + nq * 8;
            cp_async16(&Bs[s][k][nq * 8], src, ok);
        }
        cp_commit();
    };

    load_stage(0, 0);
    if (KT > 1) load_stage(1, 1);
    for (int kt = 0; kt < KT; kt++) {
        int s = kt % NSTAGE;
        if (kt + 1 < KT) asm volatile("cp.async.wait_group 1;");
        else             asm volatile("cp.async.wait_group 0;");
        __syncthreads();
        if (kt + 2 < KT) load_stage(kt + 2, (kt + 2) % NSTAGE);

#pragma unroll
        for (int kk = 0; kk < HBK; kk += 16) {
            wmma::fragment<wmma::matrix_a, 16, 16, 16, __half, wmma::row_major> af[MI];
            wmma::fragment<wmma::matrix_b, 16, 16, 16, __half, wmma::row_major> bf[2];
#pragma unroll
            for (int i = 0; i < MI; i++)
                wmma::load_matrix_sync(af[i], &As[s][wr * WM + i * 16][kk], HAP);
#pragma unroll
            for (int j = 0; j < 2; j++)
                wmma::load_matrix_sync(bf[j], &Bs[s][kk][wc * 32 + j * 16], BP);
#pragma unroll
            for (int i = 0; i < MI; i++)
#pragma unroll
                for (int j = 0; j < 2; j++)
                    wmma::mma_sync(acc[i][j], af[i], bf[j], acc[i][j]);
        }
        __syncthreads();
    }

#pragma unroll
    for (int i = 0; i < MI; i++) {
#pragma unroll
        for (int j = 0; j < 2; j++) {
            wmma::store_matrix_sync(&stage[wid][0][0], acc[i][j], 20, wmma::mem_row_major);
            __syncwarp();
            int r = lane >> 1, c0 = (lane & 1) * 8;
            int gr = bm + wr * WM + i * 16 + r;
            int gc = bn + wc * 32 + j * 16 + c0;
            float v[8];
#pragma unroll
            for (int t = 0; t < 8; t++) v[t] = stage[wid][r][c0 + t];
            if (EPI == 0) {
                __half2 h[4];
#pragma unroll
                for (int q = 0; q < 4; q++) h[q] = __floats2half2_rn(v[2 * q], v[2 * q + 1]);
                *reinterpret_cast<uint4*>((__half*)Cout + (long)gr * N + gc) =
                    *reinterpret_cast<uint4*>(h);
            } else {
                float* op = (float*)Cout + (long)gr * N + gc;
                *reinterpret_cast<float4*>(op) = make_float4(v[0], v[1], v[2], v[3]);
                *reinterpret_cast<float4*>(op + 4) = make_float4(v[4], v[5], v[6], v[7]);
                float sq[8];
#pragma unroll
                for (int t = 0; t < 8; t++) sq[t] = v[t] * v[t];
#pragma unroll
                for (int o = 16; o > 1; o >>= 1) {
#pragma unroll
                    for (int t = 0; t < 8; t++) {
                        v[t]  += __shfl_down_sync(0xffffffffu, v[t], o);
                        sq[t] += __shfl_down_sync(0xffffffffu, sq[t], o);
                    }
                }
                if (lane < 2) {
                    int cl = wc * 32 + j * 16 + c0;
#pragma unroll
                    for (int t = 0; t < 8; t++) {
                        atomicAdd(&csum[cl + t], v[t]);
                        atomicAdd(&csq[cl + t], sq[t]);
                    }
                }
            }
            __syncwarp();
        }
    }
    if (EPI == 2) {
        __syncthreads();
        if (tid < F3) {
            atomicAdd(&g_bnsum[tid], csum[tid]);
            atomicAdd(&g_bnsq[tid], csq[tid]);
        }
    }
}

// ---------------- CSR build (parallel two-kernel scan) ----------------
__global__ void hist_k(const int* __restrict__ ei) {
    int e = blockIdx.x * blockDim.x + threadIdx.x;
    if (e >= E_TOT) return;
    int d = (e < E_RAW) ? ei[E_RAW + e] : e - E_RAW;
    atomicAdd(&g_deg[d], 1);
}
__global__ void scanA_k() {
    __shared__ int sh[SCAN_B];
    int i = blockIdx.x * SCAN_B + threadIdx.x;
    int v = (i < NN) ? g_deg[i] : 0;
    sh[threadIdx.x] = v;
    __syncthreads();
    for (int o = 1; o < SCAN_B; o <<= 1) {
        int t = 0;
        if (threadIdx.x >= o) t = sh[threadIdx.x - o];
        __syncthreads();
        if (threadIdx.x >= o) sh[threadIdx.x] += t;
        __syncthreads();
    }
    if (i < NN) g_rowptr[i] = sh[threadIdx.x] - v;
    if (threadIdx.x == SCAN_B - 1) g_bsum[blockIdx.x] = sh[SCAN_B - 1];
}
__global__ void scanC_k() {
    __shared__ int pre;
    if (threadIdx.x == 0) pre = 0;
    __syncthreads();
    if (threadIdx.x < blockIdx.x) atomicAdd(&pre, g_bsum[threadIdx.x]);
    __syncthreads();
    int i = blockIdx.x * SCAN_B + threadIdx.x;
    if (i < NN) g_rowptr[i] += pre;
    if (i == 0) g_rowptr[NN] = E_TOT;
}
__global__ void scatter_k(const int* __restrict__ ei) {
    int e = blockIdx.x * blockDim.x + threadIdx.x;
    if (e >= E_TOT) return;
    int s, d;
    if (e < E_RAW) { s = ei[e]; d = ei[E_RAW + e]; } else { s = d = e - E_RAW; }
    int pos = g_rowptr[d] + atomicAdd(&g_cur[d], 1);
    g_csrc[pos] = s;
}

// ---------------- fused GAT layer (fp16, single-pass softmax, node-range) ----------------
template <int C, bool NEXT_ATT>
__global__ void gat_fused_h(const float* __restrict__ as_, const float* __restrict__ ad_,
                            const __half* __restrict__ hsrc, const float* __restrict__ bias,
                            __half* __restrict__ out,
                            const float* __restrict__ nvs, const float* __restrict__ nvd,
                            float* __restrict__ nas, float* __restrict__ nad,
                            int n0, int n1) {
    constexpr int CPL = C / 32;
    int w = n0 + blockIdx.x * (blockDim.x >> 5) + (threadIdx.x >> 5);
    int lane = threadIdx.x & 31;
    if (w >= n1) return;
    int r0 = g_rowptr[w], r1 = g_rowptr[w + 1];
    float add = ad_[w];

    float ac[CPL];
#pragma unroll
    for (int t = 0; t < CPL; t++) ac[t] = 0.f;
    float den = 0.f;

    for (int base = r0; base < r1; base += 32) {
        int i = base + lane;
        int s = 0; float wgt = 0.f;
        if (i < r1) {
            s = g_csrc[i];
            float e = as_[s] + add;
            e = e >= 0.f ? e : 0.2f * e;
            wgt = __expf(e);
        }
        den += wgt;
        int cnt = min(32, r1 - base);
        for (int j = 0; j < cnt; j++) {
            int sj = __shfl_sync(0xffffffffu, s, j);
            float wj = __shfl_sync(0xffffffffu, wgt, j);
            const __half* hp = hsrc + (long)sj * C + lane * CPL;
            if (CPL == 8) {
                uint4 raw = *reinterpret_cast<const uint4*>(hp);
                const __half2* ph = reinterpret_cast<const __half2*>(&raw);
#pragma unroll
                for (int q = 0; q < 4; q++) {
                    float2 f = __half22float2(ph[q]);
                    ac[2 * q]     = fmaf(wj, f.x, ac[2 * q]);
                    ac[2 * q + 1] = fmaf(wj, f.y, ac[2 * q + 1]);
                }
            } else {
                uint2 raw = *reinterpret_cast<const uint2*>(hp);
                const __half2* ph = reinterpret_cast<const __half2*>(&raw);
#pragma unroll
                for (int q = 0; q < 2; q++) {
                    float2 f = __half22float2(ph[q]);
                    ac[2 * q]     = fmaf(wj, f.x, ac[2 * q]);
                    ac[2 * q + 1] = fmaf(wj, f.y, ac[2 * q + 1]);
                }
            }
        }
    }
#pragma unroll
    for (int o = 16; o > 0; o >>= 1) den += __shfl_xor_sync(0xffffffffu, den, o);
    float inv = 1.f / (den + 1e-16f);

    float r[CPL];
#pragma unroll
    for (int t = 0; t < CPL; t++) {
        float b = bias[lane * CPL + t];
        r[t] = fmaxf(fmaf(ac[t], inv, b), 0.f);
    }
    __half2 hpak[CPL / 2];
#pragma unroll
    for (int q = 0; q < CPL / 2; q++) hpak[q] = __floats2half2_rn(r[2 * q], r[2 * q + 1]);
    __half* op = out + (long)w * C + lane * CPL;
    if (CPL == 8) *reinterpret_cast<uint4*>(op) = *reinterpret_cast<uint4*>(hpak);
    else          *reinterpret_cast<uint2*>(op) = *reinterpret_cast<uint2*>(hpak);

    if (NEXT_ATT) {
        float s2 = 0.f, d2 = 0.f;
#pragma unroll
        for (int t = 0; t < CPL; t++) {
            int c = lane * CPL + t;
            s2 += r[t] * nvs[c];
            d2 += r[t] * nvd[c];
        }
#pragma unroll
        for (int o = 16; o > 0; o >>= 1) {
            s2 += __shfl_down_sync(0xffffffffu, s2, o);
            d2 += __shfl_down_sync(0xffffffffu, d2, o);
        }
        if (lane == 0) { nas[w] = s2; nad[w] = d2; }
    }
}

// ---------------- head (bn_final folded in: each block recomputes scale/shift) ----------------
__global__ void head_k(const float* __restrict__ h3, const float* __restrict__ fc2w,
                       const float* __restrict__ fc2b, const float* __restrict__ bng,
                       const float* __restrict__ bnb, float* __restrict__ out, int n) {
    __shared__ float sw[F3 * OUTC];
    __shared__ float ssc[F3], ssh[F3];
    int tid = threadIdx.x;
    if (tid < F3) {
        float inv = 1.f / (float)n;
        float mu = g_bnsum[tid] * inv;
        float var = g_bnsq[tid] * inv - mu * mu;
        float sc = bng[tid] * rsqrtf(var + 1e-5f);
        ssc[tid] = sc;
        ssh[tid] = bnb[tid] - mu * sc;
    }
    for (int i = tid; i < F3 * OUTC; i += blockDim.x) sw[i] = fc2w[i];
    __syncthreads();
    int row = blockIdx.x * blockDim.x + tid;
    if (row >= n) return;
    float y[4] = {fc2b[0], fc2b[1], fc2b[2], fc2b[3]};
    const float4* hr = reinterpret_cast<const float4*>(h3 + (long)row * F3);
#pragma unroll
    for (int c4 = 0; c4 < F3 / 4; c4++) {
        float4 x4 = hr[c4];
        float xs[4] = {x4.x, x4.y, x4.z, x4.w};
#pragma unroll
        for (int u = 0; u < 4; u++) {
            int c = c4 * 4 + u;
            float v = fmaxf(xs[u] * ssc[c] + ssh[c], 0.f);
#pragma unroll
            for (int o = 0; o < 4; o++) y[o] = fmaf(v, sw[c * 4 + o], y[o]);
        }
    }
    float mx = fmaxf(fmaxf(y[0], y[1]), fmaxf(y[2], y[3]));
    float se = expf(y[0] - mx) + expf(y[1] - mx) + expf(y[2] - mx) + expf(y[3] - mx);
    float l = mx + logf(se);
    float* op = out + (long)row * OUTC;
    op[0] = y[0] - l; op[1] = y[1] - l; op[2] = y[2] - l; op[3] = y[3] - l;
}

// ---------------- launch ----------------
#define SYM(p, s) do { void* _t; cudaGetSymbolAddress(&_t, s); p = (decltype(p))_t; } while (0)

extern "C" void kernel_launch(void* const* d_in, const int* in_sizes, int n_in,
                              void* d_out, int out_size) {
    const float* x    = (const float*)d_in[0];
    const int*   ei   = (const int*)d_in[1];
    const float* linw = (const float*)d_in[2];
    const float* linb = (const float*)d_in[3];
    const float* w1s  = (const float*)d_in[4];
    const float* w1d  = (const float*)d_in[5];
    const float* a1s  = (const float*)d_in[6];
    const float* a1d  = (const float*)d_in[7];
    const float* b1   = (const float*)d_in[8];
    const float* w2s  = (const float*)d_in[9];
    const float* w2d  = (const float*)d_in[10];
    const float* a2s  = (const float*)d_in[11];
    const float* a2d  = (const float*)d_in[12];
    const float* b2   = (const float*)d_in[13];
    const float* fc1w = (const float*)d_in[14];
    // d_in[15] = fc1_b: cancels in BatchNorm, unused
    const float* bng  = (const float*)d_in[16];
    const float* bnb  = (const float*)d_in[17];
    const float* fc2w = (const float*)d_in[18];
    const float* fc2b = (const float*)d_in[19];
    float* out = (float*)d_out;

    __half *out1h, *hsrch, *hsrc2h, *out2h, *w2h, *wfh;
    float *h3, *as_, *ad_, *as2, *ad2, *v2s, *v2d;
    SYM(hsrch, g_hsrch); SYM(out1h, g_out1h);
    SYM(hsrc2h, g_hsrc2h); SYM(out2h, g_out2h); SYM(h3, g_h3);
    SYM(w2h, g_w2h); SYM(wfh, g_wfh);
    SYM(as_, g_as); SYM(ad_, g_ad); SYM(as2, g_as2); SYM(ad2, g_ad2);
    SYM(v2s, g_v2s); SYM(v2d, g_v2d);

    const int MBY = NNP / 128;          // 782
    const int EB = (E_TOT + 255) / 256;

    static cudaStream_t s2 = nullptr;
    static cudaEvent_t evFork = nullptr, evJoin = nullptr, evA = nullptr, evJ2 = nullptr;
    if (!s2) {
        cudaStreamCreateWithFlags(&s2, cudaStreamNonBlocking);
        cudaEventCreateWithFlags(&evFork, cudaEventDisableTiming);
        cudaEventCreateWithFlags(&evJoin, cudaEventDisableTiming);
        cudaEventCreateWithFlags(&evA, cudaEventDisableTiming);
        cudaEventCreateWithFlags(&evJ2, cudaEventDisableTiming);
    }

    // 1: conversions + zeroing + attention matvecs
    prep_k<<<(NN + 255) / 256, 256>>>(linw, w1s, w2s, fc1w, a1s, w1d, a1d, a2s, w2d, a2d);

    // fork: CSR build on side stream, overlapped with fused_l01
    cudaEventRecord(evFork, 0);
    cudaStreamWaitEvent(s2, evFork, 0);
    hist_k<<<EB, 256, 0, s2>>>(ei);
    scanA_k<<<NBLK, SCAN_B, 0, s2>>>();
    scanC_k<<<NBLK, SCAN_B, 0, s2>>>();
    scatter_k<<<EB, 256, 0, s2>>>(ei);
    cudaEventRecord(evJoin, s2);

    // main: fused lin GEMM + dual matvec + l1 h_src GEMM
    fused_l01<<<NNP / 64, 256>>>(x, linb);
    cudaStreamWaitEvent(0, evJoin, 0);

    // ---- GAT layer 1 in two chunks; l2 GEMM of chunk A overlaps chunk B ----
    gat_fused_h<C1, true><<<(NSPLIT + 7) / 8, 256>>>(as_, ad_, hsrch, b1, out1h,
                                                     v2s, v2d, as2, ad2, 0, NSPLIT);
    cudaEventRecord(evA, 0);
    cudaStreamWaitEvent(s2, evA, 0);
    hgemm_tc<128, 0><<<dim3(1, MSPLIT), 256, 0, s2>>>(out1h, w2h, hsrc2h, NNP, C1, C2, 0);
    cudaEventRecord(evJ2, s2);

    gat_fused_h<C1, true><<<(NN - NSPLIT + 7) / 8, 256>>>(as_, ad_, hsrch, b1, out1h,
                                                          v2s, v2d, as2, ad2, NSPLIT, NN);
    hgemm_tc<128, 0><<<dim3(1, MBY - MSPLIT), 256>>>(out1h, w2h, hsrc2h, NNP, C1, C2, MSPLIT);
    cudaStreamWaitEvent(0, evJ2, 0);

    // ---- GAT layer 2 (full) ----
    gat_fused_h<C2, false><<<(NN + 7) / 8, 256>>>(as2, ad2, hsrc2h, b2, out2h,
                                                  nullptr, nullptr, nullptr, nullptr, 0, NN);

    // ---- head: fc1 GEMM with fused BN stats; bn_final folded into head_k ----
    hgemm_tc<64, 2><<<dim3(F3 / 64, MBY), 256>>>(out2h, wfh, h3, NNP, C2, F3, 0);
    head_k<<<(NN + 127) / 128, 128>>>(h3, fc2w, fc2b, bng, bnb, out, NN);
}

// round 17
// speedup vs baseline: 1.0256x; 1.0256x over previous
#include <cuda_runtime.h>
#include <cuda_fp16.h>
#include <mma.h>
#include <math.h>

using namespace nvcuda;

#define NN 100000
#define NNP 100096
#define E_RAW 800000
#define E_TOT 900000
#define F_IN 300
#define KXP 304
#define C1 256
#define C2 128
#define F3 64
#define OUTC 4
#define SCAN_B 1024
#define NBLK ((NN + SCAN_B - 1) / SCAN_B)   // 98

// ---------------- scratch ----------------
__device__ __half g_hsrch[(long)NNP * C1];
__device__ __half g_out1h[(long)NNP * C1];
__device__ __half g_hsrc2h[(long)NNP * C2];
__device__ __half g_out2h[(long)NNP * C2];   // pad rows stay 0 (zero-init, never written)
__device__ float  g_h3[(long)NNP * F3];
// fp16 weights
__device__ __half g_wlinh[KXP * C1];
__device__ __half g_w1h[C1 * C1];
__device__ __half g_w2h[C1 * C2];
__device__ __half g_wfh[C2 * F3];
// attention
__device__ float g_as[NN], g_ad[NN];
__device__ float g_as2[NN], g_ad2[NN];
__device__ float g_v1s[C1], g_v1d[C1], g_v2s[C1], g_v2d[C1];
__device__ float g_bnsum[F3], g_bnsq[F3];
// CSR
__device__ int g_deg[NN];
__device__ int g_cur[NN];
__device__ int g_rowptr[NN + 1];
__device__ int g_bsum[NBLK];
__device__ int g_csrc[E_TOT];

// ---------------- cp.async helpers ----------------
__device__ __forceinline__ void cp_async16(void* smem_dst, const void* gsrc, int src_bytes) {
    unsigned saddr = (unsigned)__cvta_generic_to_shared(smem_dst);
    asm volatile("cp.async.cg.shared.global [%0], [%1], 16, %2;"
                 :: "r"(saddr), "l"(gsrc), "r"(src_bytes));
}
__device__ __forceinline__ void cp_commit() {
    asm volatile("cp.async.commit_group;");
}

// ---------------- prep: weight conversions + zeroing + attention matvecs ----------------
__global__ void prep_k(const float* __restrict__ linw, const float* __restrict__ w1s,
                       const float* __restrict__ w2s, const float* __restrict__ fc1w,
                       const float* __restrict__ a1s, const float* __restrict__ w1d,
                       const float* __restrict__ a1d, const float* __restrict__ a2s,
                       const float* __restrict__ w2d, const float* __restrict__ a2d) {
    int i = blockIdx.x * blockDim.x + threadIdx.x;
    if (i < KXP * C1) {
        int r = i / C1;
        g_wlinh[i] = __float2half(r < F_IN ? linw[i] : 0.f);
    }
    if (i < C1 * C1) g_w1h[i] = __float2half(w1s[i]);
    if (i < C1 * C2) g_w2h[i] = __float2half(w2s[i]);
    if (i < C2 * F3) g_wfh[i] = __float2half(fc1w[i]);
    if (i < NN) { g_deg[i] = 0; g_cur[i] = 0; }
    if (i < F3) { g_bnsum[i] = 0.f; g_bnsq[i] = 0.f; }

    if (blockIdx.x < 128) {
        int gw = blockIdx.x * 8 + (threadIdx.x >> 5);
        int lane = threadIdx.x & 31;
        const float *W, *a; float* v; int cols, row;
        if (gw < C1)            { W = w1s; a = a1s; v = g_v1s; cols = C1; row = gw; }
        else if (gw < 2 * C1)   { W = w1d; a = a1d; v = g_v1d; cols = C1; row = gw - C1; }
        else if (gw < 3 * C1)   { W = w2s; a = a2s; v = g_v2s; cols = C2; row = gw - 2 * C1; }
        else                    { W = w2d; a = a2d; v = g_v2d; cols = C2; row = gw - 3 * C1; }
        float s = 0.f;
        for (int c = lane; c < cols; c += 32) s += W[(long)row * cols + c] * a[c];
#pragma unroll
        for (int o = 16; o > 0; o >>= 1) s += __shfl_down_sync(0xffffffffu, s, o);
        if (lane == 0) v[row] = s;
    }
}

#define NSTAGE 3
#define FAP 40
#define FBP 264
#define H0P 264

// ---------------- fused: h0=relu(x@Wlin+b) -> as/ad -> hsrc=h0@W1s ----------------
__global__ void __launch_bounds__(256, 2)
fused_l01(const float* __restrict__ x, const float* __restrict__ linb) {
    __shared__ __align__(16) __half As[2][64][FAP];
    __shared__ __align__(16) __half Bs[NSTAGE][32][FBP];
    __shared__ __align__(16) __half H0[64][H0P];
    __shared__ float stage[8][16][20];

    const int tid = threadIdx.x;
    const int wid = tid >> 5;
    const int lane = tid & 31;
    const int wr = wid >> 2;
    const int wc = wid & 3;
    const int bm = blockIdx.x * 64;
    const int am = tid >> 2;
    const int akq = tid & 3;

    const int arow = bm + am;
    const bool rowok = arow < NN;
    const float* xrow = x + (long)arow * F_IN + akq * 8;

    // ---------- phase 1: H0 = relu(x @ Wlin + b) ----------
    {
        wmma::fragment<wmma::accumulator, 16, 16, 16, float> acc[2][4];
#pragma unroll
        for (int i = 0; i < 2; i++)
#pragma unroll
            for (int j = 0; j < 4; j++) wmma::fill_fragment(acc[i][j], 0.f);

        float areg[8];
        auto ld_a = [&](int kt) {
            if (rowok && kt < 9) {
                const float4* p = reinterpret_cast<const float4*>(xrow + kt * 32);
                float4 u = p[0], v = p[1];
                areg[0] = u.x; areg[1] = u.y; areg[2] = u.z; areg[3] = u.w;
                areg[4] = v.x; areg[5] = v.y; areg[6] = v.z; areg[7] = v.w;
            } else if (rowok) {
                int cbase = kt * 32 + akq * 8;
#pragma unroll
                for (int t = 0; t < 8; t++)
                    areg[t] = (cbase + t < F_IN) ? xrow[kt * 32 + t] : 0.f;
            } else {
#pragma unroll
                for (int t = 0; t < 8; t++) areg[t] = 0.f;
            }
        };
        auto st_a = [&](int s) {
            __half2 hp[4];
#pragma unroll
            for (int q = 0; q < 4; q++) hp[q] = __floats2half2_rn(areg[2 * q], areg[2 * q + 1]);
            *reinterpret_cast<uint4*>(&As[s][am][akq * 8]) = *reinterpret_cast<uint4*>(hp);
        };
        auto ls1 = [&](int kt, int s) {
            int k0 = kt * 32;
#pragma unroll
            for (int i = 0; i < 4; i++) {
                int idx = tid + i * 256;
                int k = idx >> 5, nq = idx & 31;
                int gk = k0 + k;
                int ok = (gk < KXP) ? 16 : 0;
                cp_async16(&Bs[s][k][nq * 8],
                           g_wlinh + (long)min(gk, KXP - 1) * C1 + nq * 8, ok);
            }
            cp_commit();
        };

        const int KT1 = (KXP + 31) / 32;   // 10
        ld_a(0); st_a(0);
        ls1(0, 0); ls1(1, 1);
        for (int kt = 0; kt < KT1; kt++) {
            int s = kt % NSTAGE;
            if (kt + 1 < KT1) ld_a(kt + 1);
            if (kt + 1 < KT1) asm volatile("cp.async.wait_group 1;");
            else              asm volatile("cp.async.wait_group 0;");
            __syncthreads();
            if (kt + 2 < KT1) ls1(kt + 2, (kt + 2) % NSTAGE);
#pragma unroll
            for (int kk = 0; kk < 32; kk += 16) {
                wmma::fragment<wmma::matrix_a, 16, 16, 16, __half, wmma::row_major> af[2];
#pragma unroll
                for (int i = 0; i < 2; i++)
                    wmma::load_matrix_sync(af[i], &As[kt & 1][wr * 32 + i * 16][kk], FAP);
#pragma unroll
                for (int j = 0; j < 4; j++) {
                    wmma::fragment<wmma::matrix_b, 16, 16, 16, __half, wmma::row_major> bf;
                    wmma::load_matrix_sync(bf, &Bs[s][kk][wc * 64 + j * 16], FBP);
                    wmma::mma_sync(acc[0][j], af[0], bf, acc[0][j]);
                    wmma::mma_sync(acc[1][j], af[1], bf, acc[1][j]);
                }
            }
            if (kt + 1 < KT1) st_a((kt + 1) & 1);
        }
#pragma unroll
        for (int i = 0; i < 2; i++) {
#pragma unroll
            for (int j = 0; j < 4; j++) {
                wmma::store_matrix_sync(&stage[wid][0][0], acc[i][j], 20, wmma::mem_row_major);
                __syncwarp();
                int r = lane >> 1, c0 = (lane & 1) * 8;
                int rl = wr * 32 + i * 16 + r;
                int cl = wc * 64 + j * 16 + c0;
                float v[8];
#pragma unroll
                for (int t = 0; t < 8; t++)
                    v[t] = fmaxf(stage[wid][r][c0 + t] + linb[cl + t], 0.f);
                __half2 hp[4];
#pragma unroll
                for (int q = 0; q < 4; q++) hp[q] = __floats2half2_rn(v[2 * q], v[2 * q + 1]);
                *reinterpret_cast<uint4*>(&H0[rl][cl]) = *reinterpret_cast<uint4*>(hp);
                __syncwarp();
            }
        }
    }
    __syncthreads();

    // ---------- phase 1.5: as/ad = H0 @ v1s / v1d ----------
    {
        const float4* vs4 = reinterpret_cast<const float4*>(g_v1s);
        const float4* vd4 = reinterpret_cast<const float4*>(g_v1d);
#pragma unroll
        for (int r8 = 0; r8 < 8; r8++) {
            int rl = wid * 8 + r8;
            uint4 raw = *reinterpret_cast<const uint4*>(&H0[rl][lane * 8]);
            const __half2* ph = reinterpret_cast<const __half2*>(&raw);
            float s = 0.f, d = 0.f;
#pragma unroll
            for (int q = 0; q < 4; q++) {
                float2 f = __half22float2(ph[q]);
                float4 sv = vs4[lane * 2 + (q >> 1)];
                float4 dv = vd4[lane * 2 + (q >> 1)];
                float svx = (q & 1) ? sv.z : sv.x, svy = (q & 1) ? sv.w : sv.y;
                float dvx = (q & 1) ? dv.z : dv.x, dvy = (q & 1) ? dv.w : dv.y;
                s += f.x * svx + f.y * svy;
                d += f.x * dvx + f.y * dvy;
            }
#pragma unroll
            for (int o = 16; o > 0; o >>= 1) {
                s += __shfl_down_sync(0xffffffffu, s, o);
                d += __shfl_down_sync(0xffffffffu, d, o);
            }
            int grow = bm + rl;
            if (lane == 0 && grow < NN) { g_as[grow] = s; g_ad[grow] = d; }
        }
    }

    // ---------- phase 2: hsrc = H0 @ W1s (A from smem) ----------
    {
        wmma::fragment<wmma::accumulator, 16, 16, 16, float> acc[2][4];
#pragma unroll
        for (int i = 0; i < 2; i++)
#pragma unroll
            for (int j = 0; j < 4; j++) wmma::fill_fragment(acc[i][j], 0.f);

        auto ls2 = [&](int kt, int s) {
            int k0 = kt * 32;
#pragma unroll
            for (int i = 0; i < 4; i++) {
                int idx = tid + i * 256;
                int k = idx >> 5, nq = idx & 31;
                cp_async16(&Bs[s][k][nq * 8],
                           g_w1h + (long)(k0 + k) * C1 + nq * 8, 16);
            }
            cp_commit();
        };

        const int KT2 = C1 / 32;   // 8
        ls2(0, 0); ls2(1, 1);
        for (int kt = 0; kt < KT2; kt++) {
            int s = kt % NSTAGE;
            if (kt + 1 < KT2) asm volatile("cp.async.wait_group 1;");
            else              asm volatile("cp.async.wait_group 0;");
            __syncthreads();
            if (kt + 2 < KT2) ls2(kt + 2, (kt + 2) % NSTAGE);
#pragma unroll
            for (int kk = 0; kk < 32; kk += 16) {
                wmma::fragment<wmma::matrix_a, 16, 16, 16, __half, wmma::row_major> af[2];
#pragma unroll
                for (int i = 0; i < 2; i++)
                    wmma::load_matrix_sync(af[i], &H0[wr * 32 + i * 16][kt * 32 + kk], H0P);
#pragma unroll
                for (int j = 0; j < 4; j++) {
                    wmma::fragment<wmma::matrix_b, 16, 16, 16, __half, wmma::row_major> bf;
                    wmma::load_matrix_sync(bf, &Bs[s][kk][wc * 64 + j * 16], FBP);
                    wmma::mma_sync(acc[0][j], af[0], bf, acc[0][j]);
                    wmma::mma_sync(acc[1][j], af[1], bf, acc[1][j]);
                }
            }
        }
#pragma unroll
        for (int i = 0; i < 2; i++) {
#pragma unroll
            for (int j = 0; j < 4; j++) {
                wmma::store_matrix_sync(&stage[wid][0][0], acc[i][j], 20, wmma::mem_row_major);
                __syncwarp();
                int r = lane >> 1, c0 = (lane & 1) * 8;
                int gr = bm + wr * 32 + i * 16 + r;
                int gc = wc * 64 + j * 16 + c0;
                __half2 hp[4];
#pragma unroll
                for (int q = 0; q < 4; q++)
                    hp[q] = __floats2half2_rn(stage[wid][r][c0 + 2 * q],
                                              stage[wid][r][c0 + 2 * q + 1]);
                *reinterpret_cast<uint4*>(g_hsrch + (long)gr * C1 + gc) =
                    *reinterpret_cast<uint4*>(hp);
                __syncwarp();
            }
        }
    }
}

// ---------------- fp16 GEMM (l2: EPI=0; fc1: EPI=2 fp32-out + fused BN stats) ----------------
#define HBK 32
#define HAP 40
template <int BN, int EPI>
__global__ void __launch_bounds__(256, 2)
hgemm_tc(const __half* __restrict__ A, const __half* __restrict__ B,
         void* __restrict__ Cout, int M, int K, int N) {
    constexpr int BP = BN + 8;
    constexpr int WM = (BN == 128) ? 64 : 32;
    constexpr int CG = BN / 32;
    constexpr int MI = WM / 16;
    __shared__ __align__(16) __half As[NSTAGE][128][HAP];
    __shared__ __align__(16) __half Bs[NSTAGE][HBK][BP];
    __shared__ float stage[8][16][20];
    __shared__ float csum[F3], csq[F3];

    const int tid = threadIdx.x;
    const int wid = tid >> 5;
    const int lane = tid & 31;
    const int wr = wid / CG;
    const int wc = wid % CG;
    const int bm = blockIdx.y * 128;
    const int bn = blockIdx.x * BN;
    const int KT = (K + HBK - 1) / HBK;

    if (EPI == 2 && tid < F3) { csum[tid] = 0.f; csq[tid] = 0.f; }

    wmma::fragment<wmma::accumulator, 16, 16, 16, float> acc[MI][2];
#pragma unroll
    for (int i = 0; i < MI; i++)
#pragma unroll
        for (int j = 0; j < 2; j++) wmma::fill_fragment(acc[i][j], 0.0f);

    auto load_stage = [&](int kt, int s) {
        int k0 = kt * HBK;
#pragma unroll
        for (int i = 0; i < 2; i++) {
            int idx = tid + i * 256;
            int m = idx >> 2, kq = idx & 3;
            int gr = bm + m, gk = k0 + kq * 8;
            int ok = (gr < M && gk < K) ? 16 : 0;
            const __half* src = A + (long)min(gr, M - 1) * K + min(gk, K - 8);
            cp_async16(&As[s][m][kq * 8], src, ok);
        }
#pragma unroll
        for (int i = 0; i < (HBK * BN / 8) / 256; i++) {
            int idx = tid + i * 256;
            int k = idx / (BN / 8), nq = idx % (BN / 8);
            int gk = k0 + k;
            int ok = (gk < K) ? 16 : 0;
            const __half* src = B + (long)min(gk, K - 1) * N + bn + nq * 8;
            cp_async16(&Bs[s][k][nq * 8], src, ok);
        }
        cp_commit();
    };

    load_stage(0, 0);
    if (KT > 1) load_stage(1, 1);
    for (int kt = 0; kt < KT; kt++) {
        int s = kt % NSTAGE;
        if (kt + 1 < KT) asm volatile("cp.async.wait_group 1;");
        else             asm volatile("cp.async.wait_group 0;");
        __syncthreads();
        if (kt + 2 < KT) load_stage(kt + 2, (kt + 2) % NSTAGE);

#pragma unroll
        for (int kk = 0; kk < HBK; kk += 16) {
            wmma::fragment<wmma::matrix_a, 16, 16, 16, __half, wmma::row_major> af[MI];
            wmma::fragment<wmma::matrix_b, 16, 16, 16, __half, wmma::row_major> bf[2];
#pragma unroll
            for (int i = 0; i < MI; i++)
                wmma::load_matrix_sync(af[i], &As[s][wr * WM + i * 16][kk], HAP);
#pragma unroll
            for (int j = 0; j < 2; j++)
                wmma::load_matrix_sync(bf[j], &Bs[s][kk][wc * 32 + j * 16], BP);
#pragma unroll
            for (int i = 0; i < MI; i++)
#pragma unroll
                for (int j = 0; j < 2; j++)
                    wmma::mma_sync(acc[i][j], af[i], bf[j], acc[i][j]);
        }
        __syncthreads();
    }

#pragma unroll
    for (int i = 0; i < MI; i++) {
#pragma unroll
        for (int j = 0; j < 2; j++) {
            wmma::store_matrix_sync(&stage[wid][0][0], acc[i][j], 20, wmma::mem_row_major);
            __syncwarp();
            int r = lane >> 1, c0 = (lane & 1) * 8;
            int gr = bm + wr * WM + i * 16 + r;
            int gc = bn + wc * 32 + j * 16 + c0;
            float v[8];
#pragma unroll
            for (int t = 0; t < 8; t++) v[t] = stage[wid][r][c0 + t];
            if (EPI == 0) {
                __half2 h[4];
#pragma unroll
                for (int q = 0; q < 4; q++) h[q] = __floats2half2_rn(v[2 * q], v[2 * q + 1]);
                *reinterpret_cast<uint4*>((__half*)Cout + (long)gr * N + gc) =
                    *reinterpret_cast<uint4*>(h);
            } else {
                float* op = (float*)Cout + (long)gr * N + gc;
                *reinterpret_cast<float4*>(op) = make_float4(v[0], v[1], v[2], v[3]);
                *reinterpret_cast<float4*>(op + 4) = make_float4(v[4], v[5], v[6], v[7]);
                float sq[8];
#pragma unroll
                for (int t = 0; t < 8; t++) sq[t] = v[t] * v[t];
#pragma unroll
                for (int o = 16; o > 1; o >>= 1) {
#pragma unroll
                    for (int t = 0; t < 8; t++) {
                        v[t]  += __shfl_down_sync(0xffffffffu, v[t], o);
                        sq[t] += __shfl_down_sync(0xffffffffu, sq[t], o);
                    }
                }
                if (lane < 2) {
                    int cl = wc * 32 + j * 16 + c0;
#pragma unroll
                    for (int t = 0; t < 8; t++) {
                        atomicAdd(&csum[cl + t], v[t]);
                        atomicAdd(&csq[cl + t], sq[t]);
                    }
                }
            }
            __syncwarp();
        }
    }
    if (EPI == 2) {
        __syncthreads();
        if (tid < F3) {
            atomicAdd(&g_bnsum[tid], csum[tid]);
            atomicAdd(&g_bnsq[tid], csq[tid]);
        }
    }
}

// ---------------- CSR build (parallel two-kernel scan) ----------------
__global__ void hist_k(const int* __restrict__ ei) {
    int e = blockIdx.x * blockDim.x + threadIdx.x;
    if (e >= E_TOT) return;
    int d = (e < E_RAW) ? ei[E_RAW + e] : e - E_RAW;
    atomicAdd(&g_deg[d], 1);
}
__global__ void scanA_k() {
    __shared__ int sh[SCAN_B];
    int i = blockIdx.x * SCAN_B + threadIdx.x;
    int v = (i < NN) ? g_deg[i] : 0;
    sh[threadIdx.x] = v;
    __syncthreads();
    for (int o = 1; o < SCAN_B; o <<= 1) {
        int t = 0;
        if (threadIdx.x >= o) t = sh[threadIdx.x - o];
        __syncthreads();
        if (threadIdx.x >= o) sh[threadIdx.x] += t;
        __syncthreads();
    }
    if (i < NN) g_rowptr[i] = sh[threadIdx.x] - v;
    if (threadIdx.x == SCAN_B - 1) g_bsum[blockIdx.x] = sh[SCAN_B - 1];
}
__global__ void scanC_k() {
    __shared__ int pre;
    if (threadIdx.x == 0) pre = 0;
    __syncthreads();
    if (threadIdx.x < blockIdx.x) atomicAdd(&pre, g_bsum[threadIdx.x]);
    __syncthreads();
    int i = blockIdx.x * SCAN_B + threadIdx.x;
    if (i < NN) g_rowptr[i] += pre;
    if (i == 0) g_rowptr[NN] = E_TOT;
}
__global__ void scatter_k(const int* __restrict__ ei) {
    int e = blockIdx.x * blockDim.x + threadIdx.x;
    if (e >= E_TOT) return;
    int s, d;
    if (e < E_RAW) { s = ei[e]; d = ei[E_RAW + e]; } else { s = d = e - E_RAW; }
    int pos = g_rowptr[d] + atomicAdd(&g_cur[d], 1);
    g_csrc[pos] = s;
}

// ---------------- fused GAT layer (fp16, single-pass softmax) ----------------
template <int C, bool NEXT_ATT>
__global__ void gat_fused_h(const float* __restrict__ as_, const float* __restrict__ ad_,
                            const __half* __restrict__ hsrc, const float* __restrict__ bias,
                            __half* __restrict__ out,
                            const float* __restrict__ nvs, const float* __restrict__ nvd,
                            float* __restrict__ nas, float* __restrict__ nad) {
    constexpr int CPL = C / 32;
    int w = blockIdx.x * (blockDim.x >> 5) + (threadIdx.x >> 5);
    int lane = threadIdx.x & 31;
    if (w >= NN) return;
    int r0 = g_rowptr[w], r1 = g_rowptr[w + 1];
    float add = ad_[w];

    float ac[CPL];
#pragma unroll
    for (int t = 0; t < CPL; t++) ac[t] = 0.f;
    float den = 0.f;

    for (int base = r0; base < r1; base += 32) {
        int i = base + lane;
        int s = 0; float wgt = 0.f;
        if (i < r1) {
            s = g_csrc[i];
            float e = as_[s] + add;
            e = e >= 0.f ? e : 0.2f * e;
            wgt = __expf(e);
        }
        den += wgt;
        int cnt = min(32, r1 - base);
        for (int j = 0; j < cnt; j++) {
            int sj = __shfl_sync(0xffffffffu, s, j);
            float wj = __shfl_sync(0xffffffffu, wgt, j);
            const __half* hp = hsrc + (long)sj * C + lane * CPL;
            if (CPL == 8) {
                uint4 raw = *reinterpret_cast<const uint4*>(hp);
                const __half2* ph = reinterpret_cast<const __half2*>(&raw);
#pragma unroll
                for (int q = 0; q < 4; q++) {
                    float2 f = __half22float2(ph[q]);
                    ac[2 * q]     = fmaf(wj, f.x, ac[2 * q]);
                    ac[2 * q + 1] = fmaf(wj, f.y, ac[2 * q + 1]);
                }
            } else {
                uint2 raw = *reinterpret_cast<const uint2*>(hp);
                const __half2* ph = reinterpret_cast<const __half2*>(&raw);
#pragma unroll
                for (int q = 0; q < 2; q++) {
                    float2 f = __half22float2(ph[q]);
                    ac[2 * q]     = fmaf(wj, f.x, ac[2 * q]);
                    ac[2 * q + 1] = fmaf(wj, f.y, ac[2 * q + 1]);
                }
            }
        }
    }
#pragma unroll
    for (int o = 16; o > 0; o >>= 1) den += __shfl_xor_sync(0xffffffffu, den, o);
    float inv = 1.f / (den + 1e-16f);

    float r[CPL];
#pragma unroll
    for (int t = 0; t < CPL; t++) {
        float b = bias[lane * CPL + t];
        r[t] = fmaxf(fmaf(ac[t], inv, b), 0.f);
    }
    __half2 hpak[CPL / 2];
#pragma unroll
    for (int q = 0; q < CPL / 2; q++) hpak[q] = __floats2half2_rn(r[2 * q], r[2 * q + 1]);
    __half* op = out + (long)w * C + lane * CPL;
    if (CPL == 8) *reinterpret_cast<uint4*>(op) = *reinterpret_cast<uint4*>(hpak);
    else          *reinterpret_cast<uint2*>(op) = *reinterpret_cast<uint2*>(hpak);

    if (NEXT_ATT) {
        float s2 = 0.f, d2 = 0.f;
#pragma unroll
        for (int t = 0; t < CPL; t++) {
            int c = lane * CPL + t;
            s2 += r[t] * nvs[c];
            d2 += r[t] * nvd[c];
        }
#pragma unroll
        for (int o = 16; o > 0; o >>= 1) {
            s2 += __shfl_down_sync(0xffffffffu, s2, o);
            d2 += __shfl_down_sync(0xffffffffu, d2, o);
        }
        if (lane == 0) { nas[w] = s2; nad[w] = d2; }
    }
}

// ---------------- head (bn_final folded in: each block recomputes scale/shift) ----------------
__global__ void head_k(const float* __restrict__ h3, const float* __restrict__ fc2w,
                       const float* __restrict__ fc2b, const float* __restrict__ bng,
                       const float* __restrict__ bnb, float* __restrict__ out, int n) {
    __shared__ float sw[F3 * OUTC];
    __shared__ float ssc[F3], ssh[F3];
    int tid = threadIdx.x;
    if (tid < F3) {
        float inv = 1.f / (float)n;
        float mu = g_bnsum[tid] * inv;
        float var = g_bnsq[tid] * inv - mu * mu;
        float sc = bng[tid] * rsqrtf(var + 1e-5f);
        ssc[tid] = sc;
        ssh[tid] = bnb[tid] - mu * sc;
    }
    for (int i = tid; i < F3 * OUTC; i += blockDim.x) sw[i] = fc2w[i];
    __syncthreads();
    int row = blockIdx.x * blockDim.x + tid;
    if (row >= n) return;
    float y[4] = {fc2b[0], fc2b[1], fc2b[2], fc2b[3]};
    const float4* hr = reinterpret_cast<const float4*>(h3 + (long)row * F3);
#pragma unroll
    for (int c4 = 0; c4 < F3 / 4; c4++) {
        float4 x4 = hr[c4];
        float xs[4] = {x4.x, x4.y, x4.z, x4.w};
#pragma unroll
        for (int u = 0; u < 4; u++) {
            int c = c4 * 4 + u;
            float v = fmaxf(xs[u] * ssc[c] + ssh[c], 0.f);
#pragma unroll
            for (int o = 0; o < 4; o++) y[o] = fmaf(v, sw[c * 4 + o], y[o]);
        }
    }
    float mx = fmaxf(fmaxf(y[0], y[1]), fmaxf(y[2], y[3]));
    float se = expf(y[0] - mx) + expf(y[1] - mx) + expf(y[2] - mx) + expf(y[3] - mx);
    float l = mx + logf(se);
    float* op = out + (long)row * OUTC;
    op[0] = y[0] - l; op[1] = y[1] - l; op[2] = y[2] - l; op[3] = y[3] - l;
}

// ---------------- launch ----------------
#define SYM(p, s) do { void* _t; cudaGetSymbolAddress(&_t, s); p = (decltype(p))_t; } while (0)

extern "C" void kernel_launch(void* const* d_in, const int* in_sizes, int n_in,
                              void* d_out, int out_size) {
    const float* x    = (const float*)d_in[0];
    const int*   ei   = (const int*)d_in[1];
    const float* linw = (const float*)d_in[2];
    const float* linb = (const float*)d_in[3];
    const float* w1s  = (const float*)d_in[4];
    const float* w1d  = (const float*)d_in[5];
    const float* a1s  = (const float*)d_in[6];
    const float* a1d  = (const float*)d_in[7];
    const float* b1   = (const float*)d_in[8];
    const float* w2s  = (const float*)d_in[9];
    const float* w2d  = (const float*)d_in[10];
    const float* a2s  = (const float*)d_in[11];
    const float* a2d  = (const float*)d_in[12];
    const float* b2   = (const float*)d_in[13];
    const float* fc1w = (const float*)d_in[14];
    // d_in[15] = fc1_b: cancels in BatchNorm, unused
    const float* bng  = (const float*)d_in[16];
    const float* bnb  = (const float*)d_in[17];
    const float* fc2w = (const float*)d_in[18];
    const float* fc2b = (const float*)d_in[19];
    float* out = (float*)d_out;

    __half *out1h, *hsrch, *hsrc2h, *out2h, *w2h, *wfh;
    float *h3, *as_, *ad_, *as2, *ad2, *v2s, *v2d;
    SYM(hsrch, g_hsrch); SYM(out1h, g_out1h);
    SYM(hsrc2h, g_hsrc2h); SYM(out2h, g_out2h); SYM(h3, g_h3);
    SYM(w2h, g_w2h); SYM(wfh, g_wfh);
    SYM(as_, g_as); SYM(ad_, g_ad); SYM(as2, g_as2); SYM(ad2, g_ad2);
    SYM(v2s, g_v2s); SYM(v2d, g_v2d);

    const int MBY = NNP / 128;          // 782
    const int EB = (E_TOT + 255) / 256;
    const int WB = (NN + 7) / 8;

    static cudaStream_t s2 = nullptr;
    static cudaEvent_t evFork = nullptr, evJoin = nullptr;
    if (!s2) {
        cudaStreamCreateWithFlags(&s2, cudaStreamNonBlocking);
        cudaEventCreateWithFlags(&evFork, cudaEventDisableTiming);
        cudaEventCreateWithFlags(&evJoin, cudaEventDisableTiming);
    }

    // 1: conversions + zeroing + attention matvecs
    prep_k<<<(NN + 255) / 256, 256>>>(linw, w1s, w2s, fc1w, a1s, w1d, a1d, a2s, w2d, a2d);

    // fork: CSR build on side stream, overlapped with fused_l01
    cudaEventRecord(evFork, 0);
    cudaStreamWaitEvent(s2, evFork, 0);
    hist_k<<<EB, 256, 0, s2>>>(ei);
    scanA_k<<<NBLK, SCAN_B, 0, s2>>>();
    scanC_k<<<NBLK, SCAN_B, 0, s2>>>();
    scatter_k<<<EB, 256, 0, s2>>>(ei);
    cudaEventRecord(evJoin, s2);

    // main: fused lin GEMM + dual matvec + l1 h_src GEMM
    fused_l01<<<NNP / 64, 256>>>(x, linb);
    cudaStreamWaitEvent(0, evJoin, 0);

    // ---- GAT layer 1 (epilogue computes layer-2 attention logits) ----
    gat_fused_h<C1, true><<<WB, 256>>>(as_, ad_, hsrch, b1, out1h, v2s, v2d, as2, ad2);

    // ---- GAT layer 2 ----
    hgemm_tc<128, 0><<<dim3(C2 / 128, MBY), 256>>>(out1h, w2h, hsrc2h, NNP, C1, C2);
    gat_fused_h<C2, false><<<WB, 256>>>(as2, ad2, hsrc2h, b2, out2h,
                                        nullptr, nullptr, nullptr, nullptr);

    // ---- head: fc1 GEMM with fused BN stats; bn_final folded into head_k ----
    hgemm_tc<64, 2><<<dim3(F3 / 64, MBY), 256>>>(out2h, wfh, h3, NNP, C2, F3);
    head_k<<<(NN + 127) / 128, 128>>>(h3, fc2w, fc2b, bng, bnb, out, NN);
}